// round 13
// baseline (speedup 1.0000x reference)
#include <cuda_runtime.h>
#include <cuda_bf16.h>
#include <cstdint>

// Pooling_2D_density_3D: out[b] = sum_k P_k X P_k^T, K=81 one-hot projectors,
// I=16, O=8, J=4, B=16 -> X:(16,1024,1024), out:(16,256,256).
//
// Closed form (verified rel_err ~1.2e-8): each output quad is a sum of 1-4
// gathered input quads. With u = global thread id == linear output float4
// index, the source base (quad units) is a bit-permutation of u with four
// DISJOINT shifted fields:
//   base = ((u&7)<<1) | ((u&0xF8)<<2) | ((u&0x700)<<3) | ((u&0x3F800)<<4)
// and the four source quads sit at CONSTANT offsets from base:
//   B      = base + 0      iff (i_r==i_c && j_r==j_c)   [1/64 threads]
//   C      = base + 1025   iff (i_r==i_c)               [8/64 threads]
//   D      = base + 16400  iff (j_r==j_c)               [8/64 threads]
//   center = base + 17425  always
// 49/64 threads execute only the center load.
//
// Since u = bid*256 + tid, bits 8+ come from bid: the bid half of the
// permutation is warp-uniform (uniform datapath), leaving only 4 thread ops
// before the majority path's single LDG. Store is streaming (.cs): output is
// write-once, keep the input set resident in L2 across graph replays.
//
// FINAL after 12 rounds. This form holds the best profiled duration (6.21us)
// of all variants. Run-to-run wall noise (+/-1.5us; byte-identical kernels
// drew 6.24 and 8.96) exceeds every structural delta observed across 12
// diverse variants (MLP scaling, branch-free masked FMA, unconditional loads,
// f32x2 packing, ch-pair amortization, grid shapes). 256-bit loads can't help
// (live quads sit 32B apart), reads have zero reuse, the 2x sector waste is
// structural; the kernel sits on the launch/ramp/DVFS floor.

__device__ __forceinline__ void stcs4(float4* p, float4 v)
{
    asm volatile("st.global.cs.v4.f32 [%0], {%1,%2,%3,%4};"
                 :: "l"(p), "f"(v.x), "f"(v.y), "f"(v.z), "f"(v.w) : "memory");
}

__global__ __launch_bounds__(256, 8)
void pool2d_density_kernel(const float4* __restrict__ xq, float4* __restrict__ oq)
{
    const unsigned tid = threadIdx.x;
    const unsigned bid = blockIdx.x;

    // warp-uniform half of the permutation: u bits 8-17 = bid bits 0-9
    //   (u&0x700)<<3 | (u&0x3F800)<<4  ==  ((bid&7)<<11) | ((bid>>3)<<15)
    const unsigned ubase = ((bid & 7u) << 11) | ((bid >> 3) << 15);

    // per-thread half: u bits 0-7 = tid
    const unsigned tbase = ((tid & 7u) << 1) | ((tid & 0xF8u) << 2);

    const float4* __restrict__ p = xq + (ubase | tbase);

    // center term: always present, issued at minimum depth
    float4 acc = __ldg(p + 17425);

    // match predicates (bid side warp-uniform)
    const bool im = ((bid >> 3) & 7u) == ((tid >> 3) & 7u);
    const bool jm = (bid & 7u) == (tid & 7u);

    if (im) {                                   // C group (8/64 threads)
        float4 v = __ldg(p + 1025);
        if (jm) {                               // B group (1/64 threads)
            float4 w = __ldg(p);
            v.x += w.x; v.y += w.y; v.z += w.z; v.w += w.w;
        }
        acc.x += v.x; acc.y += v.y; acc.z += v.z; acc.w += v.w;
    }
    if (jm) {                                   // D group (8/64 threads)
        float4 v = __ldg(p + 16400);
        acc.x += v.x; acc.y += v.y; acc.z += v.z; acc.w += v.w;
    }

    // store address == u (linear): fully coalesced 128B streaming stores
    stcs4(oq + (bid * 256u + tid), acc);
}

extern "C" void kernel_launch(void* const* d_in, const int* in_sizes, int n_in,
                              void* d_out, int out_size)
{
    const float4* x = (const float4*)d_in[0];   // (16, 1024, 1024) fp32 as quads
    float4* out = (float4*)d_out;               // (16, 256, 256) fp32 as quads

    // 262144 output quads, 1 per thread: 1024 blocks x 256 threads
    // (~7 blocks/SM, single wave).
    pool2d_density_kernel<<<1024, 256>>>(x, out);
}